// round 15
// baseline (speedup 1.0000x reference)
#include <cuda_runtime.h>
#include <math.h>
#include <float.h>

// Problem constants
constexpr int Bb  = 64;
constexpr int Ss  = 32;
constexpr int Dd  = 512;
constexpr int Nn  = 4096;
constexpr int Kt  = 4;
constexpr int BSD = Bb * Ss * Dd;     // 1,048,576
constexpr int MROWS1 = Kt * Bb * Ss;  // 8192  (layer1 rows, k-major)
constexpr int MROWS2 = Bb * Ss;       // 2048  (layer2 rows)

// ---------------- device scratch (static, allowed) ----------------
__device__ __align__(16) float g_mean [2][Nn * Dd];
__device__ __align__(16) float g_mnv  [2][Nn * Dd];   // normalized mean * valid
__device__ __align__(16) float g_qmean[2][Bb * Dd];
__device__ __align__(16) float g_qn   [2][Bb * Dd];
__device__ __align__(16) float g_sim  [2][Bb * Nn];
__device__            int    g_idx  [2][Bb * Kt];
__device__ __align__(16) float g_rmean[2][Bb * Dd];
__device__ __align__(16) float g_tmean[2][Bb * Kt * Dd];
__device__            float  g_score[2][Bb * Kt];
__device__ __align__(16) float g_H    [2][MROWS1 * Dd];
__device__ __align__(16) float g_gen  [2][BSD];

// ---------------- means over S for memory banks ----------------
// grid (Nn, 2), 256 threads; each thread owns 2 columns (d = 2t, 2t+1)
__global__ void mem_mean_kernel(const float* __restrict__ mem0,
                                const float* __restrict__ mem1) {
    const int mod = blockIdx.y;
    const float* mem = mod ? mem1 : mem0;
    const int n = blockIdx.x;
    const int t = threadIdx.x;
    const float* base = mem + (size_t)n * Ss * Dd + t * 2;

    float a0 = 0.f, a1 = 0.f;
#pragma unroll
    for (int s = 0; s < Ss; s++) {
        float2 v = *(const float2*)(base + s * Dd);
        a0 += v.x; a1 += v.y;
    }
    a0 *= (1.f / Ss); a1 *= (1.f / Ss);

    __shared__ float red[256];
    red[t] = a0 + a1;
    __syncthreads();
    for (int o = 128; o > 0; o >>= 1) { if (t < o) red[t] += red[t + o]; __syncthreads(); }
    const float tot = red[0];
    __syncthreads();
    red[t] = a0 * a0 + a1 * a1;
    __syncthreads();
    for (int o = 128; o > 0; o >>= 1) { if (t < o) red[t] += red[t + o]; __syncthreads(); }
    const float nrm = sqrtf(red[0]);
    const float scale = ((tot != 0.f) ? 1.f : 0.f) / fmaxf(nrm, 1e-8f);

    float* mp = g_mean[mod] + n * Dd + t * 2;
    float* vp = g_mnv [mod] + n * Dd + t * 2;
    mp[0] = a0;          mp[1] = a1;
    vp[0] = a0 * scale;  vp[1] = a1 * scale;
}

// ---------------- means over S for queries ----------------
// grid (Bb, 2): mod 0 query = text, mod 1 query = image
__global__ void q_mean_kernel(const float* __restrict__ q0,
                              const float* __restrict__ q1) {
    const int mod = blockIdx.y;
    const float* q = mod ? q1 : q0;
    const int b = blockIdx.x;
    const int t = threadIdx.x;
    const float* base = q + (size_t)b * Ss * Dd + t * 2;

    float a0 = 0.f, a1 = 0.f;
#pragma unroll
    for (int s = 0; s < Ss; s++) {
        float2 v = *(const float2*)(base + s * Dd);
        a0 += v.x; a1 += v.y;
    }
    a0 *= (1.f / Ss); a1 *= (1.f / Ss);

    __shared__ float red[256];
    red[t] = a0 * a0 + a1 * a1;
    __syncthreads();
    for (int o = 128; o > 0; o >>= 1) { if (t < o) red[t] += red[t + o]; __syncthreads(); }
    const float nrm = sqrtf(red[0]);
    const float scale = 1.f / fmaxf(nrm, 1e-8f);

    float* mp = g_qmean[mod] + b * Dd + t * 2;
    float* np = g_qn   [mod] + b * Dd + t * 2;
    mp[0] = a0;          mp[1] = a1;
    np[0] = a0 * scale;  np[1] = a1 * scale;
}

// ---------------- generic NT GEMM: C[m,n] = sum_k A[m,k]*B[n,k] (+epilogue) ----
// MODE 0: sim       A=g_qn,    B=g_mnv (global),         C=g_sim (ldc=4096)
// MODE 1: rmean     A=g_qmean, B=rem_w, +bias,           C=g_rmean
// MODE 4: tmean     A=g_mean gathered via g_idx, B=ret_w,+bias, C=g_tmean
// MODE 2: layer1    A=memory gathered (k,b,s rows), B=ew1[k], +bias relu, C=g_H
// MODE 3: layer2    A=score[b,k]*H (K=2048), B=ew2[k], +sum_k score*eb2,  C=g_gen
template<int BM, int BN, int BK, int TM, int TN, int MODE, int KD, int LDC>
__global__ void gemm_nt(const float* __restrict__ Bw0, const float* __restrict__ Bw1,
                        const float* __restrict__ bias0, const float* __restrict__ bias1,
                        const float* __restrict__ mem0, const float* __restrict__ mem1) {
    constexpr int NT = (BM / TM) * (BN / TN);
    const int mod = blockIdx.z;
    const int m0 = blockIdx.x * BM;
    const int n0 = blockIdx.y * BN;
    const int tid = threadIdx.x;
    const int tx = tid % (BN / TN);
    const int ty = tid / (BN / TN);

    const float* Bw   = mod ? Bw1 : Bw0;
    const float* bias = mod ? bias1 : bias0;
    const float* memp = mod ? mem1 : mem0;
    const int* idxp = g_idx[mod];

    const float* A;
    float* C;
    if (MODE == 0)      { A = g_qn[mod];    C = g_sim[mod];   Bw = g_mnv[mod]; }
    else if (MODE == 1) { A = g_qmean[mod]; C = g_rmean[mod]; }
    else if (MODE == 4) { A = g_mean[mod];  C = g_tmean[mod]; }
    else if (MODE == 2) { A = memp;         C = g_H[mod]; }
    else                { A = g_H[mod];     C = g_gen[mod]; }

    __shared__ __align__(16) float As[BK][BM];
    __shared__ __align__(16) float Bs[BK][BN];
    __shared__ float sSc[Bb * Kt];

    if (MODE == 3) {
        for (int i = tid; i < Bb * Kt; i += NT) sSc[i] = g_score[mod][i];
        __syncthreads();
    }

    float acc[TM][TN];
#pragma unroll
    for (int i = 0; i < TM; i++)
#pragma unroll
        for (int j = 0; j < TN; j++) acc[i][j] = 0.f;

    for (int kk0 = 0; kk0 < KD; kk0 += BK) {
        // ---- A tile (store transposed) ----
        constexpr int AV = BM * BK / 4;
#pragma unroll
        for (int i = tid; i < AV; i += NT) {
            const int r  = i / (BK / 4);
            const int c4 = (i % (BK / 4)) * 4;
            const int rg = m0 + r;
            const float* src;
            float sc = 1.f;
            if (MODE == 0 || MODE == 1) {
                src = A + (size_t)rg * KD + kk0 + c4;
            } else if (MODE == 4) {
                src = A + (size_t)idxp[rg] * Dd + kk0 + c4;
            } else if (MODE == 2) {
                const int k   = rg >> 11;          // row block of 2048 per expert
                const int loc = rg & 2047;
                const int mrow = idxp[(loc >> 5) * Kt + k];
                src = A + ((size_t)mrow * Ss + (loc & 31)) * Dd + kk0 + c4;
            } else { // MODE 3
                const int k  = kk0 >> 9;
                const int e0 = kk0 & 511;
                src = A + ((size_t)(k * MROWS2 + rg)) * Dd + e0 + c4;
                sc = sSc[(rg >> 5) * Kt + k];
            }
            const float4 v = *(const float4*)src;
            As[c4 + 0][r] = v.x * sc;
            As[c4 + 1][r] = v.y * sc;
            As[c4 + 2][r] = v.z * sc;
            As[c4 + 3][r] = v.w * sc;
        }
        // ---- B tile (store transposed) ----
        constexpr int BV = BN * BK / 4;
#pragma unroll
        for (int i = tid; i < BV; i += NT) {
            const int r  = i / (BK / 4);
            const int c4 = (i % (BK / 4)) * 4;
            const float* src;
            if (MODE == 2) {
                src = Bw + (size_t)(m0 >> 11) * Dd * Dd + (size_t)(n0 + r) * Dd + kk0 + c4;
            } else if (MODE == 3) {
                const int k  = kk0 >> 9;
                const int e0 = kk0 & 511;
                src = Bw + (size_t)k * Dd * Dd + (size_t)(n0 + r) * Dd + e0 + c4;
            } else {
                src = Bw + (size_t)(n0 + r) * KD + kk0 + c4;
            }
            const float4 v = *(const float4*)src;
            Bs[c4 + 0][r] = v.x;
            Bs[c4 + 1][r] = v.y;
            Bs[c4 + 2][r] = v.z;
            Bs[c4 + 3][r] = v.w;
        }
        __syncthreads();

#pragma unroll
        for (int kk = 0; kk < BK; kk++) {
            float ra[TM], rb[TN];
#pragma unroll
            for (int i = 0; i < TM; i += 4)
                *(float4*)&ra[i] = *(const float4*)&As[kk][ty * TM + i];
#pragma unroll
            for (int j = 0; j < TN; j += 4)
                *(float4*)&rb[j] = *(const float4*)&Bs[kk][tx * TN + j];
#pragma unroll
            for (int i = 0; i < TM; i++)
#pragma unroll
                for (int j = 0; j < TN; j++) acc[i][j] += ra[i] * rb[j];
        }
        __syncthreads();
    }

    // ---- epilogue ----
#pragma unroll
    for (int i = 0; i < TM; i++) {
        const int rg = m0 + ty * TM + i;
#pragma unroll
        for (int j = 0; j < TN; j++) {
            const int n = n0 + tx * TN + j;
            float v = acc[i][j];
            if (MODE == 1 || MODE == 4) v += bias[n];
            if (MODE == 2) { v += bias[(m0 >> 11) * Dd + n]; v = fmaxf(v, 0.f); }
            if (MODE == 3) {
                float bb = 0.f;
#pragma unroll
                for (int k = 0; k < Kt; k++) bb += sSc[(rg >> 5) * Kt + k] * bias[k * Dd + n];
                v += bb;
            }
            C[(size_t)rg * LDC + n] = v;
        }
    }
}

// ---------------- top-4 per (mod, b) with jax tie-break (lower index first) ---
__device__ __forceinline__ bool better(float a, int ai, float b, int bi) {
    return (a > b) || (a == b && ai < bi);
}

__global__ void topk_kernel() {
    const int mod = blockIdx.y;
    const int b = blockIdx.x;
    const int t = threadIdx.x;
    const float* sim = g_sim[mod] + b * Nn;

    float v[Kt]; int ix[Kt];
#pragma unroll
    for (int q = 0; q < Kt; q++) { v[q] = -FLT_MAX; ix[q] = 0x7fffffff; }

    for (int n = t; n < Nn; n += 256) {
        const float s = sim[n];
        if (better(s, n, v[Kt - 1], ix[Kt - 1])) {
            v[Kt - 1] = s; ix[Kt - 1] = n;
#pragma unroll
            for (int q = Kt - 1; q > 0; q--) {
                if (better(v[q], ix[q], v[q - 1], ix[q - 1])) {
                    float tv = v[q]; v[q] = v[q - 1]; v[q - 1] = tv;
                    int ti = ix[q]; ix[q] = ix[q - 1]; ix[q - 1] = ti;
                }
            }
        }
    }

    __shared__ float sv[256 * Kt];
    __shared__ int   si[256 * Kt];
#pragma unroll
    for (int q = 0; q < Kt; q++) { sv[t * Kt + q] = v[q]; si[t * Kt + q] = ix[q]; }
    __syncthreads();

    // tree merge of sorted top-4 lists
    for (int o = 128; o > 0; o >>= 1) {
        if (t < o) {
            float ov[Kt]; int oi[Kt];
#pragma unroll
            for (int q = 0; q < Kt; q++) { ov[q] = sv[(t + o) * Kt + q]; oi[q] = si[(t + o) * Kt + q]; }
            float mv[Kt]; int mi[Kt];
            int p = 0, q2 = 0;
#pragma unroll
            for (int z = 0; z < Kt; z++) {
                if (better(v[p], ix[p], ov[q2], oi[q2])) { mv[z] = v[p]; mi[z] = ix[p]; p++; }
                else                                     { mv[z] = ov[q2]; mi[z] = oi[q2]; q2++; }
            }
#pragma unroll
            for (int z = 0; z < Kt; z++) {
                v[z] = mv[z]; ix[z] = mi[z];
                sv[t * Kt + z] = mv[z]; si[t * Kt + z] = mi[z];
            }
        }
        __syncthreads();
    }

    if (t == 0) {
#pragma unroll
        for (int q = 0; q < Kt; q++) g_idx[mod][b * Kt + q] = ix[q];
    }
}

// ---------------- routing score: softmax_k( dot(r_mean[b], t_mean[b,k]) ) -----
__global__ void score_kernel() {
    const int mod = blockIdx.y;
    const int b = blockIdx.x;
    const int t = threadIdx.x;       // 128 threads: warp w handles expert k=w
    const int w = t >> 5, l = t & 31;

    const float* r  = g_rmean[mod] + b * Dd;
    const float* tm = g_tmean[mod] + (b * Kt + w) * Dd;
    float acc = 0.f;
    for (int d = l; d < Dd; d += 32) acc += r[d] * tm[d];
#pragma unroll
    for (int o = 16; o > 0; o >>= 1) acc += __shfl_xor_sync(0xffffffff, acc, o);

    __shared__ float lg[Kt];
    if (l == 0) lg[w] = acc;
    __syncthreads();
    if (t == 0) {
        float mx = lg[0];
#pragma unroll
        for (int k = 1; k < Kt; k++) mx = fmaxf(mx, lg[k]);
        float e[Kt], sum = 0.f;
#pragma unroll
        for (int k = 0; k < Kt; k++) { e[k] = expf(lg[k] - mx); sum += e[k]; }
        const float inv = 1.f / sum;
#pragma unroll
        for (int k = 0; k < Kt; k++) g_score[mod][b * Kt + k] = e[k] * inv;
    }
}

// ---------------- final masking / output assembly ----------------
// out = [completed_image | completed_text | gen_image_full | gen_text_full]
__global__ void assemble_kernel(const float* __restrict__ image,
                                const float* __restrict__ text,
                                const int* __restrict__ m1,
                                const int* __restrict__ m2,
                                float* __restrict__ out) {
    const int total4 = BSD / 4;
    const int i4 = blockIdx.x * blockDim.x + threadIdx.x;
    if (i4 >= total4) return;
    const int b = (i4 * 4) >> 14;    // / (S*D = 16384)
    const bool m1e = (m1[b] == 1);
    const bool m2e = (m2[b] == 1);

    const float4 gi = ((const float4*)g_gen[0])[i4];
    const float4 gt = ((const float4*)g_gen[1])[i4];
    const float4 im = ((const float4*)image)[i4];
    const float4 tx = ((const float4*)text)[i4];
    const float4 z = make_float4(0.f, 0.f, 0.f, 0.f);

    ((float4*)out)[i4]              = (!m1e && m2e) ? gi : im;
    ((float4*)out)[total4 + i4]     = (!m2e && m1e) ? gt : tx;
    ((float4*)out)[2 * total4 + i4] = m2e ? gi : z;
    ((float4*)out)[3 * total4 + i4] = m1e ? gt : z;
}

// ---------------- host launcher (graph-capturable, alloc-free) ----------------
extern "C" void kernel_launch(void* const* d_in, const int* in_sizes, int n_in,
                              void* d_out, int out_size) {
    (void)in_sizes; (void)n_in; (void)out_size;
    const float* image    = (const float*)d_in[0];
    const float* text     = (const float*)d_in[1];
    const int*   m1       = (const int*)  d_in[2];
    const int*   m2       = (const int*)  d_in[3];
    const float* mem_img  = (const float*)d_in[4];
    const float* mem_txt  = (const float*)d_in[5];
    const float* img_rem_w = (const float*)d_in[6];
    const float* img_rem_b = (const float*)d_in[7];
    const float* img_ret_w = (const float*)d_in[8];
    const float* img_ret_b = (const float*)d_in[9];
    const float* img_ew1   = (const float*)d_in[10];
    const float* img_eb1   = (const float*)d_in[11];
    const float* img_ew2   = (const float*)d_in[12];
    const float* img_eb2   = (const float*)d_in[13];
    const float* txt_rem_w = (const float*)d_in[14];
    const float* txt_rem_b = (const float*)d_in[15];
    const float* txt_ret_w = (const float*)d_in[16];
    const float* txt_ret_b = (const float*)d_in[17];
    const float* txt_ew1   = (const float*)d_in[18];
    const float* txt_eb1   = (const float*)d_in[19];
    const float* txt_ew2   = (const float*)d_in[20];
    const float* txt_eb2   = (const float*)d_in[21];
    float* out = (float*)d_out;

    // mod 0: generate IMAGE from text  (query=text,  memory=mem_image, img_* weights)
    // mod 1: generate TEXT  from image (query=image, memory=mem_text,  txt_* weights)

    // 1) means (+norms +valid) of memory banks and queries
    mem_mean_kernel<<<dim3(Nn, 2), 256>>>(mem_img, mem_txt);
    q_mean_kernel<<<dim3(Bb, 2), 256>>>(text, image);

    // 2) cosine similarity GEMM: sim[b,n] = qn . mnv
    gemm_nt<64, 128, 16, 4, 8, 0, 512, 4096>
        <<<dim3(1, Nn / 128, 2), 256>>>(nullptr, nullptr, nullptr, nullptr, nullptr, nullptr);

    // 3) top-4 retrieval indices
    topk_kernel<<<dim3(Bb, 2), 256>>>();

    // 4) r_mean = q_mean @ rem_w^T + rem_b   (linearity: mean commutes with Linear)
    gemm_nt<64, 128, 16, 4, 8, 1, 512, 512>
        <<<dim3(1, 4, 2), 256>>>(img_rem_w, txt_rem_w, img_rem_b, txt_rem_b, nullptr, nullptr);

    // 5) t_mean = gather(mem_mean, idx) @ ret_w^T + ret_b   ([256,512] rows)
    gemm_nt<64, 128, 16, 4, 8, 4, 512, 512>
        <<<dim3(4, 4, 2), 256>>>(img_ret_w, txt_ret_w, img_ret_b, txt_ret_b, nullptr, nullptr);

    // 6) routing softmax scores
    score_kernel<<<dim3(Bb, 2), 128>>>();

    // 7) expert layer 1: H = relu(gather(mem, idx) @ ew1[k]^T + eb1[k])  [8192,512]
    gemm_nt<128, 128, 16, 8, 8, 2, 512, 512>
        <<<dim3(MROWS1 / 128, 4, 2), 256>>>(img_ew1, txt_ew1, img_eb1, txt_eb1, mem_img, mem_txt);

    // 8) expert layer 2 + score-weighted combine (score folded into K=2048 reduction)
    gemm_nt<128, 64, 16, 8, 4, 3, 2048, 512>
        <<<dim3(MROWS2 / 128, 8, 2), 256>>>(img_ew2, txt_ew2, img_eb2, txt_eb2, nullptr, nullptr);

    // 9) masks + 4-way output assembly
    assemble_kernel<<<(BSD / 4 + 255) / 256, 256>>>(image, text, m1, m2, out);
}

// round 16
// speedup vs baseline: 1.0018x; 1.0018x over previous
#include <cuda_runtime.h>
#include <math.h>
#include <float.h>

// Problem constants
constexpr int Bb  = 64;
constexpr int Ss  = 32;
constexpr int Dd  = 512;
constexpr int Nn  = 4096;
constexpr int Kt  = 4;
constexpr int BSD = Bb * Ss * Dd;     // 1,048,576
constexpr int MROWS1 = Kt * Bb * Ss;  // 8192  (layer1 rows, k-major)
constexpr int MROWS2 = Bb * Ss;       // 2048  (layer2 rows)

// ---------------- device scratch (static, allowed) ----------------
__device__ __align__(16) float g_mean [2][Nn * Dd];
__device__ __align__(16) float g_mnv  [2][Nn * Dd];   // normalized mean * valid
__device__ __align__(16) float g_qmean[2][Bb * Dd];
__device__ __align__(16) float g_qn   [2][Bb * Dd];
__device__ __align__(16) float g_sim  [2][Bb * Nn];
__device__            int    g_idx  [2][Bb * Kt];
__device__ __align__(16) float g_rmean[2][Bb * Dd];
__device__ __align__(16) float g_tmean[2][Bb * Kt * Dd];
__device__            float  g_score[2][Bb * Kt];
__device__ __align__(16) float g_H    [2][MROWS1 * Dd];
__device__ __align__(16) float g_gen  [2][BSD];

// ---------------- means over S for memory banks ----------------
// grid (Nn, 2), 256 threads; each thread owns 2 columns (d = 2t, 2t+1)
__global__ void mem_mean_kernel(const float* __restrict__ mem0,
                                const float* __restrict__ mem1) {
    const int mod = blockIdx.y;
    const float* mem = mod ? mem1 : mem0;
    const int n = blockIdx.x;
    const int t = threadIdx.x;
    const float* base = mem + (size_t)n * Ss * Dd + t * 2;

    float a0 = 0.f, a1 = 0.f;
#pragma unroll
    for (int s = 0; s < Ss; s++) {
        float2 v = *(const float2*)(base + s * Dd);
        a0 += v.x; a1 += v.y;
    }
    a0 *= (1.f / Ss); a1 *= (1.f / Ss);

    __shared__ float red[256];
    red[t] = a0 + a1;
    __syncthreads();
    for (int o = 128; o > 0; o >>= 1) { if (t < o) red[t] += red[t + o]; __syncthreads(); }
    const float tot = red[0];
    __syncthreads();
    red[t] = a0 * a0 + a1 * a1;
    __syncthreads();
    for (int o = 128; o > 0; o >>= 1) { if (t < o) red[t] += red[t + o]; __syncthreads(); }
    const float nrm = sqrtf(red[0]);
    const float scale = ((tot != 0.f) ? 1.f : 0.f) / fmaxf(nrm, 1e-8f);

    float* mp = g_mean[mod] + n * Dd + t * 2;
    float* vp = g_mnv [mod] + n * Dd + t * 2;
    mp[0] = a0;          mp[1] = a1;
    vp[0] = a0 * scale;  vp[1] = a1 * scale;
}

// ---------------- means over S for queries ----------------
// grid (Bb, 2): mod 0 query = text, mod 1 query = image
__global__ void q_mean_kernel(const float* __restrict__ q0,
                              const float* __restrict__ q1) {
    const int mod = blockIdx.y;
    const float* q = mod ? q1 : q0;
    const int b = blockIdx.x;
    const int t = threadIdx.x;
    const float* base = q + (size_t)b * Ss * Dd + t * 2;

    float a0 = 0.f, a1 = 0.f;
#pragma unroll
    for (int s = 0; s < Ss; s++) {
        float2 v = *(const float2*)(base + s * Dd);
        a0 += v.x; a1 += v.y;
    }
    a0 *= (1.f / Ss); a1 *= (1.f / Ss);

    __shared__ float red[256];
    red[t] = a0 * a0 + a1 * a1;
    __syncthreads();
    for (int o = 128; o > 0; o >>= 1) { if (t < o) red[t] += red[t + o]; __syncthreads(); }
    const float nrm = sqrtf(red[0]);
    const float scale = 1.f / fmaxf(nrm, 1e-8f);

    float* mp = g_qmean[mod] + b * Dd + t * 2;
    float* np = g_qn   [mod] + b * Dd + t * 2;
    mp[0] = a0;          mp[1] = a1;
    np[0] = a0 * scale;  np[1] = a1 * scale;
}

// ---------------- generic NT GEMM: C[m,n] = sum_k A[m,k]*B[n,k] (+epilogue) ----
// MODE 0: sim       A=g_qn,    B=g_mnv (global),         C=g_sim (ldc=4096)
// MODE 1: rmean     A=g_qmean, B=rem_w, +bias,           C=g_rmean
// MODE 4: tmean     A=g_mean gathered via g_idx, B=ret_w,+bias, C=g_tmean
// MODE 2: layer1    A=memory gathered (k,b,s rows), B=ew1[k], +bias relu, C=g_H
// MODE 3: layer2    A=score[b,k]*H (K=2048), B=ew2[k], +sum_k score*eb2,  C=g_gen
template<int BM, int BN, int BK, int TM, int TN, int MODE, int KD, int LDC>
__global__ void gemm_nt(const float* __restrict__ Bw0, const float* __restrict__ Bw1,
                        const float* __restrict__ bias0, const float* __restrict__ bias1,
                        const float* __restrict__ mem0, const float* __restrict__ mem1) {
    constexpr int NT = (BM / TM) * (BN / TN);
    const int mod = blockIdx.z;
    const int m0 = blockIdx.x * BM;
    const int n0 = blockIdx.y * BN;
    const int tid = threadIdx.x;
    const int tx = tid % (BN / TN);
    const int ty = tid / (BN / TN);

    const float* Bw   = mod ? Bw1 : Bw0;
    const float* bias = mod ? bias1 : bias0;
    const float* memp = mod ? mem1 : mem0;
    const int* idxp = g_idx[mod];

    const float* A;
    float* C;
    if (MODE == 0)      { A = g_qn[mod];    C = g_sim[mod];   Bw = g_mnv[mod]; }
    else if (MODE == 1) { A = g_qmean[mod]; C = g_rmean[mod]; }
    else if (MODE == 4) { A = g_mean[mod];  C = g_tmean[mod]; }
    else if (MODE == 2) { A = memp;         C = g_H[mod]; }
    else                { A = g_H[mod];     C = g_gen[mod]; }

    __shared__ __align__(16) float As[BK][BM];
    __shared__ __align__(16) float Bs[BK][BN];
    __shared__ float sSc[Bb * Kt];

    if (MODE == 3) {
        for (int i = tid; i < Bb * Kt; i += NT) sSc[i] = g_score[mod][i];
        __syncthreads();
    }

    float acc[TM][TN];
#pragma unroll
    for (int i = 0; i < TM; i++)
#pragma unroll
        for (int j = 0; j < TN; j++) acc[i][j] = 0.f;

    for (int kk0 = 0; kk0 < KD; kk0 += BK) {
        // ---- A tile (store transposed) ----
        constexpr int AV = BM * BK / 4;
#pragma unroll
        for (int i = tid; i < AV; i += NT) {
            const int r  = i / (BK / 4);
            const int c4 = (i % (BK / 4)) * 4;
            const int rg = m0 + r;
            const float* src;
            float sc = 1.f;
            if (MODE == 0 || MODE == 1) {
                src = A + (size_t)rg * KD + kk0 + c4;
            } else if (MODE == 4) {
                src = A + (size_t)idxp[rg] * Dd + kk0 + c4;
            } else if (MODE == 2) {
                const int k   = rg >> 11;          // row block of 2048 per expert
                const int loc = rg & 2047;
                const int mrow = idxp[(loc >> 5) * Kt + k];
                src = A + ((size_t)mrow * Ss + (loc & 31)) * Dd + kk0 + c4;
            } else { // MODE 3
                const int k  = kk0 >> 9;
                const int e0 = kk0 & 511;
                src = A + ((size_t)(k * MROWS2 + rg)) * Dd + e0 + c4;
                sc = sSc[(rg >> 5) * Kt + k];
            }
            const float4 v = *(const float4*)src;
            As[c4 + 0][r] = v.x * sc;
            As[c4 + 1][r] = v.y * sc;
            As[c4 + 2][r] = v.z * sc;
            As[c4 + 3][r] = v.w * sc;
        }
        // ---- B tile (store transposed) ----
        constexpr int BV = BN * BK / 4;
#pragma unroll
        for (int i = tid; i < BV; i += NT) {
            const int r  = i / (BK / 4);
            const int c4 = (i % (BK / 4)) * 4;
            const float* src;
            if (MODE == 2) {
                src = Bw + (size_t)(m0 >> 11) * Dd * Dd + (size_t)(n0 + r) * Dd + kk0 + c4;
            } else if (MODE == 3) {
                const int k  = kk0 >> 9;
                const int e0 = kk0 & 511;
                src = Bw + (size_t)k * Dd * Dd + (size_t)(n0 + r) * Dd + e0 + c4;
            } else {
                src = Bw + (size_t)(n0 + r) * KD + kk0 + c4;
            }
            const float4 v = *(const float4*)src;
            Bs[c4 + 0][r] = v.x;
            Bs[c4 + 1][r] = v.y;
            Bs[c4 + 2][r] = v.z;
            Bs[c4 + 3][r] = v.w;
        }
        __syncthreads();

#pragma unroll
        for (int kk = 0; kk < BK; kk++) {
            float ra[TM], rb[TN];
#pragma unroll
            for (int i = 0; i < TM; i += 4)
                *(float4*)&ra[i] = *(const float4*)&As[kk][ty * TM + i];
#pragma unroll
            for (int j = 0; j < TN; j += 4)
                *(float4*)&rb[j] = *(const float4*)&Bs[kk][tx * TN + j];
#pragma unroll
            for (int i = 0; i < TM; i++)
#pragma unroll
                for (int j = 0; j < TN; j++) acc[i][j] += ra[i] * rb[j];
        }
        __syncthreads();
    }

    // ---- epilogue ----
#pragma unroll
    for (int i = 0; i < TM; i++) {
        const int rg = m0 + ty * TM + i;
#pragma unroll
        for (int j = 0; j < TN; j++) {
            const int n = n0 + tx * TN + j;
            float v = acc[i][j];
            if (MODE == 1 || MODE == 4) v += bias[n];
            if (MODE == 2) { v += bias[(m0 >> 11) * Dd + n]; v = fmaxf(v, 0.f); }
            if (MODE == 3) {
                float bb = 0.f;
#pragma unroll
                for (int k = 0; k < Kt; k++) bb += sSc[(rg >> 5) * Kt + k] * bias[k * Dd + n];
                v += bb;
            }
            C[(size_t)rg * LDC + n] = v;
        }
    }
}

// ---------------- top-4 per (mod, b) with jax tie-break (lower index first) ---
__device__ __forceinline__ bool better(float a, int ai, float b, int bi) {
    return (a > b) || (a == b && ai < bi);
}

__global__ void topk_kernel() {
    const int mod = blockIdx.y;
    const int b = blockIdx.x;
    const int t = threadIdx.x;
    const float* sim = g_sim[mod] + b * Nn;

    float v[Kt]; int ix[Kt];
#pragma unroll
    for (int q = 0; q < Kt; q++) { v[q] = -FLT_MAX; ix[q] = 0x7fffffff; }

    for (int n = t; n < Nn; n += 256) {
        const float s = sim[n];
        if (better(s, n, v[Kt - 1], ix[Kt - 1])) {
            v[Kt - 1] = s; ix[Kt - 1] = n;
#pragma unroll
            for (int q = Kt - 1; q > 0; q--) {
                if (better(v[q], ix[q], v[q - 1], ix[q - 1])) {
                    float tv = v[q]; v[q] = v[q - 1]; v[q - 1] = tv;
                    int ti = ix[q]; ix[q] = ix[q - 1]; ix[q - 1] = ti;
                }
            }
        }
    }

    __shared__ float sv[256 * Kt];
    __shared__ int   si[256 * Kt];
#pragma unroll
    for (int q = 0; q < Kt; q++) { sv[t * Kt + q] = v[q]; si[t * Kt + q] = ix[q]; }
    __syncthreads();

    // tree merge of sorted top-4 lists
    for (int o = 128; o > 0; o >>= 1) {
        if (t < o) {
            float ov[Kt]; int oi[Kt];
#pragma unroll
            for (int q = 0; q < Kt; q++) { ov[q] = sv[(t + o) * Kt + q]; oi[q] = si[(t + o) * Kt + q]; }
            float mv[Kt]; int mi[Kt];
            int p = 0, q2 = 0;
#pragma unroll
            for (int z = 0; z < Kt; z++) {
                if (better(v[p], ix[p], ov[q2], oi[q2])) { mv[z] = v[p]; mi[z] = ix[p]; p++; }
                else                                     { mv[z] = ov[q2]; mi[z] = oi[q2]; q2++; }
            }
#pragma unroll
            for (int z = 0; z < Kt; z++) {
                v[z] = mv[z]; ix[z] = mi[z];
                sv[t * Kt + z] = mv[z]; si[t * Kt + z] = mi[z];
            }
        }
        __syncthreads();
    }

    if (t == 0) {
#pragma unroll
        for (int q = 0; q < Kt; q++) g_idx[mod][b * Kt + q] = ix[q];
    }
}

// ---------------- routing score: softmax_k( dot(r_mean[b], t_mean[b,k]) ) -----
__global__ void score_kernel() {
    const int mod = blockIdx.y;
    const int b = blockIdx.x;
    const int t = threadIdx.x;       // 128 threads: warp w handles expert k=w
    const int w = t >> 5, l = t & 31;

    const float* r  = g_rmean[mod] + b * Dd;
    const float* tm = g_tmean[mod] + (b * Kt + w) * Dd;
    float acc = 0.f;
    for (int d = l; d < Dd; d += 32) acc += r[d] * tm[d];
#pragma unroll
    for (int o = 16; o > 0; o >>= 1) acc += __shfl_xor_sync(0xffffffff, acc, o);

    __shared__ float lg[Kt];
    if (l == 0) lg[w] = acc;
    __syncthreads();
    if (t == 0) {
        float mx = lg[0];
#pragma unroll
        for (int k = 1; k < Kt; k++) mx = fmaxf(mx, lg[k]);
        float e[Kt], sum = 0.f;
#pragma unroll
        for (int k = 0; k < Kt; k++) { e[k] = expf(lg[k] - mx); sum += e[k]; }
        const float inv = 1.f / sum;
#pragma unroll
        for (int k = 0; k < Kt; k++) g_score[mod][b * Kt + k] = e[k] * inv;
    }
}

// ---------------- final masking / output assembly ----------------
// out = [completed_image | completed_text | gen_image_full | gen_text_full]
__global__ void assemble_kernel(const float* __restrict__ image,
                                const float* __restrict__ text,
                                const int* __restrict__ m1,
                                const int* __restrict__ m2,
                                float* __restrict__ out) {
    const int total4 = BSD / 4;
    const int i4 = blockIdx.x * blockDim.x + threadIdx.x;
    if (i4 >= total4) return;
    const int b = (i4 * 4) >> 14;    // / (S*D = 16384)
    const bool m1e = (m1[b] == 1);
    const bool m2e = (m2[b] == 1);

    const float4 gi = ((const float4*)g_gen[0])[i4];
    const float4 gt = ((const float4*)g_gen[1])[i4];
    const float4 im = ((const float4*)image)[i4];
    const float4 tx = ((const float4*)text)[i4];
    const float4 z = make_float4(0.f, 0.f, 0.f, 0.f);

    ((float4*)out)[i4]              = (!m1e && m2e) ? gi : im;
    ((float4*)out)[total4 + i4]     = (!m2e && m1e) ? gt : tx;
    ((float4*)out)[2 * total4 + i4] = m2e ? gi : z;
    ((float4*)out)[3 * total4 + i4] = m1e ? gt : z;
}

// ---------------- host launcher (graph-capturable, alloc-free) ----------------
extern "C" void kernel_launch(void* const* d_in, const int* in_sizes, int n_in,
                              void* d_out, int out_size) {
    (void)in_sizes; (void)n_in; (void)out_size;
    const float* image    = (const float*)d_in[0];
    const float* text     = (const float*)d_in[1];
    const int*   m1       = (const int*)  d_in[2];
    const int*   m2       = (const int*)  d_in[3];
    const float* mem_img  = (const float*)d_in[4];
    const float* mem_txt  = (const float*)d_in[5];
    const float* img_rem_w = (const float*)d_in[6];
    const float* img_rem_b = (const float*)d_in[7];
    const float* img_ret_w = (const float*)d_in[8];
    const float* img_ret_b = (const float*)d_in[9];
    const float* img_ew1   = (const float*)d_in[10];
    const float* img_eb1   = (const float*)d_in[11];
    const float* img_ew2   = (const float*)d_in[12];
    const float* img_eb2   = (const float*)d_in[13];
    const float* txt_rem_w = (const float*)d_in[14];
    const float* txt_rem_b = (const float*)d_in[15];
    const float* txt_ret_w = (const float*)d_in[16];
    const float* txt_ret_b = (const float*)d_in[17];
    const float* txt_ew1   = (const float*)d_in[18];
    const float* txt_eb1   = (const float*)d_in[19];
    const float* txt_ew2   = (const float*)d_in[20];
    const float* txt_eb2   = (const float*)d_in[21];
    float* out = (float*)d_out;

    // mod 0: generate IMAGE from text  (query=text,  memory=mem_image, img_* weights)
    // mod 1: generate TEXT  from image (query=image, memory=mem_text,  txt_* weights)

    // 1) means (+norms +valid) of memory banks and queries
    mem_mean_kernel<<<dim3(Nn, 2), 256>>>(mem_img, mem_txt);
    q_mean_kernel<<<dim3(Bb, 2), 256>>>(text, image);

    // 2) cosine similarity GEMM: sim[b,n] = qn . mnv
    gemm_nt<64, 128, 16, 4, 8, 0, 512, 4096>
        <<<dim3(1, Nn / 128, 2), 256>>>(nullptr, nullptr, nullptr, nullptr, nullptr, nullptr);

    // 3) top-4 retrieval indices
    topk_kernel<<<dim3(Bb, 2), 256>>>();

    // 4) r_mean = q_mean @ rem_w^T + rem_b   (linearity: mean commutes with Linear)
    gemm_nt<64, 128, 16, 4, 8, 1, 512, 512>
        <<<dim3(1, 4, 2), 256>>>(img_rem_w, txt_rem_w, img_rem_b, txt_rem_b, nullptr, nullptr);

    // 5) t_mean = gather(mem_mean, idx) @ ret_w^T + ret_b   ([256,512] rows)
    gemm_nt<64, 128, 16, 4, 8, 4, 512, 512>
        <<<dim3(4, 4, 2), 256>>>(img_ret_w, txt_ret_w, img_ret_b, txt_ret_b, nullptr, nullptr);

    // 6) routing softmax scores
    score_kernel<<<dim3(Bb, 2), 128>>>();

    // 7) expert layer 1: H = relu(gather(mem, idx) @ ew1[k]^T + eb1[k])  [8192,512]
    gemm_nt<128, 128, 16, 8, 8, 2, 512, 512>
        <<<dim3(MROWS1 / 128, 4, 2), 256>>>(img_ew1, txt_ew1, img_eb1, txt_eb1, mem_img, mem_txt);

    // 8) expert layer 2 + score-weighted combine (score folded into K=2048 reduction)
    gemm_nt<128, 64, 16, 8, 4, 3, 2048, 512>
        <<<dim3(MROWS2 / 128, 8, 2), 256>>>(img_ew2, txt_ew2, img_eb2, txt_eb2, nullptr, nullptr);

    // 9) masks + 4-way output assembly
    assemble_kernel<<<(BSD / 4 + 255) / 256, 256>>>(image, text, m1, m2, out);
}